// round 7
// baseline (speedup 1.0000x reference)
#include <cuda_runtime.h>
#include <math.h>

#define BB 16
#define HH 512
#define WW 512
#define NTOT (BB * HH * WW)

#define TILE 64
#define GX (WW / TILE)     // 8
#define GY (HH / TILE)     // 8
#define NB (GX * GY * BB)  // 1024
#define NB1 1024           // K1 blocks
#define LCAP 256
#define HROWS 84           // halo rows i0-10 .. i0+73

// Scratch (no allocation allowed in kernel_launch)
__device__ unsigned g_mask[BB * HH * 16];  // fg bitmask, 16 u32 words per row
__device__ float g_pf[NB1];   // K1: exact focal partials
__device__ float g_pl[NB1];   // K1: base loss partials (h=0 for bg, exact for fg)
__device__ float g_pc[NB];    // K2: loss correction partials
__device__ unsigned g_done = 0;

// ---------------------------------------------------------------------------
// K1: stream inp+tgt once. Builds fg bitmask AND computes:
//   fsum exact:  pos ? 0.85 q^2 : 0.15 p^2          (focal never depends on h)
//   lsum base:   pos ? 0.85 q^4 : 0.15 p^4          (fg h=1 exact; bg h=0)
// Branch-free: s = pos?q:p, a = pos?0.85:0.15, f=a*s^2, l=f*s^2.
// 16 px/thread, 8 independent LDG.128, no barriers until the block reduce.
// ---------------------------------------------------------------------------
__global__ __launch_bounds__(256) void k1_base(const float* __restrict__ inp,
                                               const float* __restrict__ tgt) {
    const int tid = threadIdx.x;
    const int gid = blockIdx.x * 256 + tid;
    const int row = gid >> 5;
    const int c16 = gid & 31;
    const size_t base = (size_t)row * WW + c16 * 16;
    const float4* tp = (const float4*)(tgt + base);
    const float4* xp = (const float4*)(inp + base);
    float4 t0 = tp[0], t1 = tp[1], t2 = tp[2], t3 = tp[3];
    float4 x0 = xp[0], x1 = xp[1], x2 = xp[2], x3 = xp[3];

    unsigned m = 0;
    float fs = 0.0f, ls = 0.0f;

#define PX(tv, xv, bit)                                   \
    {                                                     \
        bool pos = (tv) > 0.5f;                           \
        m |= pos ? (1u << (bit)) : 0u;                    \
        float p = __fdividef(1.0f, 1.0f + __expf(-(xv))); \
        float s = pos ? (1.0f - p) : p;                   \
        float a = pos ? 0.85f : 0.15f;                    \
        float s2 = s * s;                                 \
        float f = a * s2;                                 \
        fs += f;                                          \
        ls += f * s2;                                     \
    }
    PX(t0.x, x0.x, 0) PX(t0.y, x0.y, 1) PX(t0.z, x0.z, 2) PX(t0.w, x0.w, 3)
    PX(t1.x, x1.x, 4) PX(t1.y, x1.y, 5) PX(t1.z, x1.z, 6) PX(t1.w, x1.w, 7)
    PX(t2.x, x2.x, 8) PX(t2.y, x2.y, 9) PX(t2.z, x2.z, 10) PX(t2.w, x2.w, 11)
    PX(t3.x, x3.x, 12) PX(t3.y, x3.y, 13) PX(t3.z, x3.z, 14) PX(t3.w, x3.w, 15)
#undef PX

    ((unsigned short*)g_mask)[(size_t)row * 32 + c16] = (unsigned short)m;

    // block reduce (warp shuffle, fixed order -> deterministic)
    __shared__ float swF[8], swL[8];
#pragma unroll
    for (int off = 16; off > 0; off >>= 1) {
        fs += __shfl_xor_sync(0xffffffffu, fs, off);
        ls += __shfl_xor_sync(0xffffffffu, ls, off);
    }
    if ((tid & 31) == 0) {
        swF[tid >> 5] = fs;
        swL[tid >> 5] = ls;
    }
    __syncthreads();
    if (tid == 0) {
        float F = 0.0f, Lv = 0.0f;
#pragma unroll
        for (int w = 0; w < 8; w++) {
            F += swF[w];
            Lv += swL[w];
        }
        g_pf[blockIdx.x] = F;
        g_pl[blockIdx.x] = Lv;
    }
}

// ---------------------------------------------------------------------------
// K2: sparse correction. Per 64x64 tile:
//  1) extract fg points (tile + 10 halo) from the L2-resident bitmask
//  2) scatter discs (dd<=100) into sdmin via atomicMin (fixed per-thread
//     disc cells, geometry hoisted; order-independent -> deterministic)
//  3) for pixel groups with any 0 < dmin < 400 (~25% of px): load inp,
//     correct the bg loss: dl = 0.15 p^2 h (h - 2p), h = exp(-dmin/8).
//     fg px (dmin==0) and far px (dmin==400) need no correction.
//  4) reduce corrections; last block folds the final scalar.
// ---------------------------------------------------------------------------
__global__ __launch_bounds__(256, 8) void k2_corr(const float* __restrict__ inp,
                                                  float* __restrict__ out) {
    const int tid = threadIdx.x;
    const int j0 = blockIdx.x * TILE;
    const int i0 = blockIdx.y * TILE;
    const int b = blockIdx.z;

    __shared__ __align__(16) int sdmin[TILE * TILE];  // 16 KB, reused in finalize
    __shared__ unsigned slist[LCAP];
    __shared__ int scnt;
    __shared__ int slast;
    __shared__ float swC[8];

    if (tid == 0) scnt = 0;
    {
        int4 init = make_int4(400, 400, 400, 400);
        int4* s4 = (int4*)sdmin;
#pragma unroll
        for (int k = 0; k < 4; k++) s4[tid + 256 * k] = init;
    }

    // fixed disc cells for this thread: e = tid, tid+256 of 21x21
    int diM0, djM0, dd0, ok0, diM1, djM1, dd1, ok1;
    {
        int a = tid / 21, c = tid - a * 21;
        int di = a - 10, dj = c - 10;
        dd0 = di * di + dj * dj;
        ok0 = dd0 <= 100;
        diM0 = di - 10;
        djM0 = dj - 10;
        int e1 = tid + 256;
        a = e1 / 21;
        c = e1 - a * 21;
        di = a - 10;
        dj = c - 10;
        dd1 = di * di + dj * dj;
        ok1 = (e1 < 441) && (dd1 <= 100);
        diM1 = di - 10;
        djM1 = dj - 10;
    }
    __syncthreads();

    // --- 1) extract points from bitmask ---
    const int q = j0 >> 5;
    const unsigned* mb = g_mask + (size_t)b * HH * 16;
    for (int e = tid; e < HROWS * 4; e += 256) {
        int rr = e >> 2;
        int wi = e & 3;
        int gr = i0 - 10 + rr;
        int gw = q - 1 + wi;
        unsigned v = 0;
        if ((unsigned)gr < HH && (unsigned)gw < 16u) v = mb[gr * 16 + gw];
        if (wi == 0) v &= 0xFFC00000u;
        if (wi == 3) v &= 0x000003FFu;
        while (v) {
            int bit = __ffs(v) - 1;
            v &= v - 1;
            int ch = 32 * wi + bit - 22;
            int k = atomicAdd(&scnt, 1);
            if (k < LCAP) slist[k] = ((unsigned)rr << 8) | (unsigned)ch;
        }
    }
    __syncthreads();
    const int L = min(scnt, LCAP);

    // --- 2) scatter discs ---
    for (int p = 0; p < L; p++) {
        unsigned pk = slist[p];
        int rp = (int)(pk >> 8);
        int cp = (int)(pk & 255u);
        if (ok0) {
            int tr = rp + diM0, tc = cp + djM0;
            if ((unsigned)tr < TILE && (unsigned)tc < TILE)
                atomicMin(&sdmin[tr * TILE + tc], dd0);
        }
        if (ok1) {
            int tr = rp + diM1, tc = cp + djM1;
            if ((unsigned)tr < TILE && (unsigned)tc < TILE)
                atomicMin(&sdmin[tr * TILE + tc], dd1);
        }
    }
    __syncthreads();

    // --- 3) sparse correction: 4 groups of 4 contiguous px per thread ---
    const float* ib = inp + ((size_t)(b * HH + i0)) * WW + j0;
    float csum = 0.0f;
#pragma unroll
    for (int it = 0; it < 4; it++) {
        int g = tid + 256 * it;       // 0..1023
        int r = g >> 4;               // tile row
        int cg = (g & 15) << 2;       // tile col base
        int4 dm = *(const int4*)&sdmin[r * TILE + cg];
        // need correction iff exists element with 0 < dm < 400
        int a0 = (dm.x == 0) ? 400 : dm.x;
        int a1 = (dm.y == 0) ? 400 : dm.y;
        int a2 = (dm.z == 0) ? 400 : dm.z;
        int a3 = (dm.w == 0) ? 400 : dm.w;
        if (min(min(a0, a1), min(a2, a3)) < 400) {
            float4 x = *(const float4*)(ib + (size_t)r * WW + cg);
#define CORR(av, xv)                                                   \
    if ((av) < 400) {                                                  \
        float p = __fdividef(1.0f, 1.0f + __expf(-(xv)));              \
        float h = __expf((float)(av) * -0.125f);                       \
        csum += p * p * h * (h - 2.0f * p);                            \
    }
            CORR(a0, x.x) CORR(a1, x.y) CORR(a2, x.z) CORR(a3, x.w)
#undef CORR
        }
    }
    csum *= 0.15f;

    // --- 4) reduce + last-block finalize ---
#pragma unroll
    for (int off = 16; off > 0; off >>= 1)
        csum += __shfl_xor_sync(0xffffffffu, csum, off);
    if ((tid & 31) == 0) swC[tid >> 5] = csum;
    __syncthreads();

    const int bid = blockIdx.x + GX * (blockIdx.y + GY * blockIdx.z);
    if (tid == 0) {
        float C = 0.0f;
#pragma unroll
        for (int w = 0; w < 8; w++) C += swC[w];
        g_pc[bid] = C;
        __threadfence();
        unsigned old = atomicAdd(&g_done, 1u);
        slast = (old == NB - 1) ? 1 : 0;
    }
    __syncthreads();

    if (slast) {
        __threadfence();
        double* sFd = (double*)sdmin;
        double* sLd = ((double*)sdmin) + 256;
        double f = 0.0, l = 0.0;
        for (int i = tid; i < NB1; i += 256) {
            f += (double)g_pf[i];
            l += (double)g_pl[i];
        }
        for (int i = tid; i < NB; i += 256) l += (double)g_pc[i];
        sFd[tid] = f;
        sLd[tid] = l;
        __syncthreads();
#pragma unroll
        for (int s = 128; s > 0; s >>= 1) {
            if (tid < s) {
                sFd[tid] += sFd[tid + s];
                sLd[tid] += sLd[tid + s];
            }
            __syncthreads();
        }
        if (tid == 0) {
            double n = (double)NTOT;
            double denom = sFd[0] / n + 0.01;
            out[0] = (float)(2.0 * (sLd[0] / n) / denom);
            g_done = 0;  // reset for next graph replay
        }
    }
}

extern "C" void kernel_launch(void* const* d_in, const int* in_sizes, int n_in,
                              void* d_out, int out_size) {
    const float* inp = (const float*)d_in[0];
    const float* tgt = (const float*)d_in[1];
    float* out = (float*)d_out;

    k1_base<<<NB1, 256>>>(inp, tgt);
    dim3 g2(GX, GY, BB);
    k2_corr<<<g2, 256>>>(inp, out);
}

// round 8
// speedup vs baseline: 1.6567x; 1.6567x over previous
#include <cuda_runtime.h>
#include <math.h>

#define BB 16
#define HH 512
#define WW 512
#define NTOT (BB * HH * WW)

#define TILE 64
#define GX (WW / TILE)     // 8
#define GY (HH / TILE)     // 8
#define NB (GX * GY * BB)  // 1024
#define LCAP 256
#define HROWS 84           // halo rows i0-10 .. i0+73

// Scratch (no allocation allowed in kernel_launch)
__device__ unsigned g_mask[BB * HH * 16];  // fg bitmask, 16 u32 words per row
__device__ float g_pl[NB];
__device__ float g_pf[NB];
__device__ unsigned g_done = 0;  // last-block counter (self-resetting)

// ---------------------------------------------------------------------------
// K1: build fg bitmask. Pure streaming: each thread loads 4 independent
// float4s (16 cols), builds 16 bits locally, stores one u16. MLP=4/thread.
// ---------------------------------------------------------------------------
__global__ __launch_bounds__(256) void k1_mask(const float* __restrict__ tgt) {
    const int gid = blockIdx.x * 256 + threadIdx.x;
    const int row = gid >> 5;
    const int c16 = gid & 31;
    const float4* p = (const float4*)(tgt + (size_t)row * WW + c16 * 16);
    float4 v0 = p[0], v1 = p[1], v2 = p[2], v3 = p[3];
    unsigned m = 0;
    m |= (v0.x > 0.5f) ? 1u << 0 : 0u;
    m |= (v0.y > 0.5f) ? 1u << 1 : 0u;
    m |= (v0.z > 0.5f) ? 1u << 2 : 0u;
    m |= (v0.w > 0.5f) ? 1u << 3 : 0u;
    m |= (v1.x > 0.5f) ? 1u << 4 : 0u;
    m |= (v1.y > 0.5f) ? 1u << 5 : 0u;
    m |= (v1.z > 0.5f) ? 1u << 6 : 0u;
    m |= (v1.w > 0.5f) ? 1u << 7 : 0u;
    m |= (v2.x > 0.5f) ? 1u << 8 : 0u;
    m |= (v2.y > 0.5f) ? 1u << 9 : 0u;
    m |= (v2.z > 0.5f) ? 1u << 10 : 0u;
    m |= (v2.w > 0.5f) ? 1u << 11 : 0u;
    m |= (v3.x > 0.5f) ? 1u << 12 : 0u;
    m |= (v3.y > 0.5f) ? 1u << 13 : 0u;
    m |= (v3.z > 0.5f) ? 1u << 14 : 0u;
    m |= (v3.w > 0.5f) ? 1u << 15 : 0u;
    ((unsigned short*)g_mask)[(size_t)row * 32 + c16] = (unsigned short)m;
}

// ---------------------------------------------------------------------------
// K2: per 64x64 tile.
//  1) extract fg points (tile + 10 halo) from the L2-resident bitmask
//  2) scatter discs (dd<=100) into sdmin via atomicMin (fixed per-thread
//     disc cells; order-independent -> deterministic)
//  3) dense branch-free epilogue, 4 rows x 4 cols per thread (LDS.128 +
//     LDG.128): p=sigmoid(inp), h=exp(-dmin/8) via MUFU; uniform bg formula
//     f=0.15p^2, l=0.15(p(p-h))^2. fg px (dmin==0, h=1 exact) get the rare
//     per-thread correction cf=0.85q^2-0.15p^2, cl=q^2*cf.
//  4) shuffle reduce; last block folds the final scalar.
// dmin=400 where no point within dist 10 -> h=exp(-50)~0; true heatmap
// there <= exp(-100/8)=3.7e-6 -> loss-equivalent well within 1e-3.
// ---------------------------------------------------------------------------
__global__ __launch_bounds__(256) void k2_main(const float* __restrict__ inp,
                                               float* __restrict__ out) {
    const int tid = threadIdx.x;
    const int j0 = blockIdx.x * TILE;
    const int i0 = blockIdx.y * TILE;
    const int b = blockIdx.z;

    __shared__ __align__(16) int sdmin[TILE * TILE];  // 16 KB, reused in finalize
    __shared__ unsigned slist[LCAP];
    __shared__ int scnt;
    __shared__ int slast;
    __shared__ float swF[8];
    __shared__ float swL[8];

    if (tid == 0) scnt = 0;
    {
        int4 init = make_int4(400, 400, 400, 400);
        int4* s4 = (int4*)sdmin;
#pragma unroll
        for (int k = 0; k < 4; k++) s4[tid + 256 * k] = init;
    }

    // fixed disc cells for this thread: e = tid, tid+256 of the 21x21 disc
    int diM0, djM0, dd0, ok0, diM1, djM1, dd1, ok1;
    {
        int a = tid / 21, c = tid - a * 21;
        int di = a - 10, dj = c - 10;
        dd0 = di * di + dj * dj;
        ok0 = dd0 <= 100;
        diM0 = di - 10;
        djM0 = dj - 10;
        int e1 = tid + 256;
        a = e1 / 21;
        c = e1 - a * 21;
        di = a - 10;
        dj = c - 10;
        dd1 = di * di + dj * dj;
        ok1 = (e1 < 441) && (dd1 <= 100);
        diM1 = di - 10;
        djM1 = dj - 10;
    }
    __syncthreads();

    // --- 1) extract points from bitmask ---
    const int q = j0 >> 5;
    const unsigned* mb = g_mask + (size_t)b * HH * 16;
    for (int e = tid; e < HROWS * 4; e += 256) {
        int rr = e >> 2;
        int wi = e & 3;
        int gr = i0 - 10 + rr;
        int gw = q - 1 + wi;
        unsigned v = 0;
        if ((unsigned)gr < HH && (unsigned)gw < 16u) v = mb[gr * 16 + gw];
        if (wi == 0) v &= 0xFFC00000u;  // keep cols >= j0-10
        if (wi == 3) v &= 0x000003FFu;  // keep cols <= j0+73
        while (v) {
            int bit = __ffs(v) - 1;
            v &= v - 1;
            int ch = 32 * wi + bit - 22;  // halo col 0..83
            int k = atomicAdd(&scnt, 1);
            if (k < LCAP) slist[k] = ((unsigned)rr << 8) | (unsigned)ch;
        }
    }
    __syncthreads();
    const int L = min(scnt, LCAP);

    // --- 2) scatter discs (order-independent atomicMin -> deterministic) ---
    for (int p = 0; p < L; p++) {
        unsigned pk = slist[p];
        int rp = (int)(pk >> 8);
        int cp = (int)(pk & 255u);
        if (ok0) {
            int tr = rp + diM0, tc = cp + djM0;
            if ((unsigned)tr < TILE && (unsigned)tc < TILE)
                atomicMin(&sdmin[tr * TILE + tc], dd0);
        }
        if (ok1) {
            int tr = rp + diM1, tc = cp + djM1;
            if ((unsigned)tr < TILE && (unsigned)tc < TILE)
                atomicMin(&sdmin[tr * TILE + tc], dd1);
        }
    }
    __syncthreads();

    // --- 3) dense epilogue: 4 rows x 4 cols per thread, branch-free ---
    const int c4 = (tid & 15) << 2;   // col 0..60
    const int r0 = (tid >> 4) << 2;   // row 0..60
    const float* ib = inp + ((size_t)(b * HH + i0 + r0)) * WW + j0 + c4;
    float fsum = 0.0f, lsum = 0.0f;
    int mnall = 400;
#pragma unroll
    for (int k = 0; k < 4; k++) {
        int4 dm = *(const int4*)&sdmin[(r0 + k) * TILE + c4];
        float4 x = *(const float4*)(ib + (size_t)k * WW);
        mnall = min(mnall, min(min(dm.x, dm.y), min(dm.z, dm.w)));
#define PXE(dv, xv)                                           \
    {                                                         \
        float p = __fdividef(1.0f, 1.0f + __expf(-(xv)));     \
        float h = __expf((float)(dv) * -0.125f);              \
        fsum = fmaf(p, p, fsum);                              \
        float d = p - h;                                      \
        float t = p * d;                                      \
        lsum = fmaf(t, t, lsum);                              \
    }
        PXE(dm.x, x.x) PXE(dm.y, x.y) PXE(dm.z, x.z) PXE(dm.w, x.w)
#undef PXE
    }
    float thF = 0.15f * fsum;
    float thL = 0.15f * lsum;

    if (mnall == 0) {  // rare: thread owns >=1 foreground pixel
        for (int k = 0; k < 4; k++) {
            int4 dm = *(const int4*)&sdmin[(r0 + k) * TILE + c4];
            float4 x = *(const float4*)(ib + (size_t)k * WW);
#define CORR(dv, xv)                                              \
    if ((dv) == 0) {                                              \
        float p = __fdividef(1.0f, 1.0f + __expf(-(xv)));         \
        float qq = 1.0f - p;                                      \
        float cf = 0.85f * qq * qq - 0.15f * p * p;               \
        thF += cf;                                                \
        thL += qq * qq * cf;                                      \
    }
            CORR(dm.x, x.x) CORR(dm.y, x.y) CORR(dm.z, x.z) CORR(dm.w, x.w)
#undef CORR
        }
    }

    // --- 4) shuffle reduction (fixed order -> deterministic) ---
#pragma unroll
    for (int off = 16; off > 0; off >>= 1) {
        thF += __shfl_xor_sync(0xffffffffu, thF, off);
        thL += __shfl_xor_sync(0xffffffffu, thL, off);
    }
    if ((tid & 31) == 0) {
        swF[tid >> 5] = thF;
        swL[tid >> 5] = thL;
    }
    __syncthreads();

    const int bid = blockIdx.x + GX * (blockIdx.y + GY * blockIdx.z);
    if (tid == 0) {
        float F = 0.0f, Lv = 0.0f;
#pragma unroll
        for (int w = 0; w < 8; w++) {
            F += swF[w];
            Lv += swL[w];
        }
        g_pf[bid] = F;
        g_pl[bid] = Lv;
        __threadfence();
        unsigned old = atomicAdd(&g_done, 1u);
        slast = (old == NB - 1) ? 1 : 0;
    }
    __syncthreads();

    // --- last block: fold final scalar (reuses sdmin as double scratch) ---
    if (slast) {
        __threadfence();
        double* sFd = (double*)sdmin;
        double* sLd = ((double*)sdmin) + 256;
        double f = 0.0, l = 0.0;
        for (int i = tid; i < NB; i += 256) {
            f += (double)g_pf[i];
            l += (double)g_pl[i];
        }
        sFd[tid] = f;
        sLd[tid] = l;
        __syncthreads();
#pragma unroll
        for (int s = 128; s > 0; s >>= 1) {
            if (tid < s) {
                sFd[tid] += sFd[tid + s];
                sLd[tid] += sLd[tid + s];
            }
            __syncthreads();
        }
        if (tid == 0) {
            double n = (double)NTOT;
            double denom = sFd[0] / n + 0.01;
            out[0] = (float)(2.0 * (sLd[0] / n) / denom);
            g_done = 0;  // reset for next graph replay
        }
    }
}

extern "C" void kernel_launch(void* const* d_in, const int* in_sizes, int n_in,
                              void* d_out, int out_size) {
    const float* inp = (const float*)d_in[0];
    const float* tgt = (const float*)d_in[1];
    float* out = (float*)d_out;

    k1_mask<<<(BB * HH * 32) / 256, 256>>>(tgt);
    dim3 g2(GX, GY, BB);
    k2_main<<<g2, 256>>>(inp, out);
}